// round 10
// baseline (speedup 1.0000x reference)
#include <cuda_runtime.h>
#include <cstdint>

// Problem constants
#define S        1048576              // 1024*1024
#define S4       (S / 4)              // 262144 float4 per slab-third / z / out
#define TPB      256
#define NSLAB    10                   // TT0:r0, TT1:r0..2, TT2:r0..2, TT3:r0..2
#define PBLK     59                   // reduce blocks per slab
#define RBLK     (NSLAB * PBLK)       // 590 blocks total (= grid, <= 4*148 resident)
#define RSTRIDE  (PBLK * TPB)         // 15104 float4 grid stride
#define NIT      18                   // 17 full + 1 ragged iteration (18*15104 >= S4)
#define NCOMP    30                   // 10 slabs x 3 q-components
#define SLICE    445                  // t4 float4s per r-slab per block (589*445+39 = S4)

// Deterministic scratch (no device allocation allowed)
__device__ float        g_bpart[NCOMP * PBLK];   // [comp][PBLK]
__device__ float        g_f[3];
__device__ unsigned int g_ctr  = 0;              // reduce-completion counter
__device__ volatile int g_flag = 0;              // f-ready flag
__device__ unsigned int g_done = 0;              // bcast-completion counter

// ---- tiny PTX helpers -----------------------------------------------------
__device__ __forceinline__ uint32_t smem_u32(const void* p) {
    uint32_t a;
    asm("{ .reg .u64 t; cvta.to.shared.u64 t, %1; cvt.u32.u64 %0, t; }"
        : "=r"(a) : "l"(p));
    return a;
}
__device__ __forceinline__ void mbar_init(uint32_t mbar, uint32_t cnt) {
    asm volatile("mbarrier.init.shared.b64 [%0], %1;" :: "r"(mbar), "r"(cnt) : "memory");
}
__device__ __forceinline__ void mbar_expect_tx(uint32_t mbar, uint32_t bytes) {
    asm volatile("mbarrier.arrive.expect_tx.shared.b64 _, [%0], %1;"
                 :: "r"(mbar), "r"(bytes) : "memory");
}
__device__ __forceinline__ void bulk_g2s(uint32_t dst, const void* src,
                                         uint32_t bytes, uint32_t mbar) {
    asm volatile("cp.async.bulk.shared::cta.global.mbarrier::complete_tx::bytes "
                 "[%0], [%1], %2, [%3];"
                 :: "r"(dst), "l"(src), "r"(bytes), "r"(mbar) : "memory");
}
__device__ __forceinline__ void mbar_wait(uint32_t mbar, uint32_t parity) {
    uint32_t done;
    asm volatile("{ .reg .pred p; "
                 "mbarrier.try_wait.parity.acquire.cta.shared::cta.b64 p, [%1], %2; "
                 "selp.b32 %0, 1, 0, p; }"
                 : "=r"(done) : "r"(mbar), "r"(parity) : "memory");
    if (!done) {
        asm volatile("{ .reg .pred P1; "
                     "WL%=: mbarrier.try_wait.parity.acquire.cta.shared::cta.b64 P1, [%0], %1, 0x989680; "
                     "@P1 bra.uni WD%=; bra.uni WL%=; WD%=: }"
                     :: "r"(mbar), "r"(parity) : "memory");
    }
}

// ---------------------------------------------------------------------------
// Single fused kernel. Grid = 590 = RBLK blocks, ALL co-resident (launch
// bounds guarantee >=4 CTAs/SM * 148 SMs = 592 slots), so spin-waiting on the
// f-ready flag is deadlock-free.
// ---------------------------------------------------------------------------
__global__ void __launch_bounds__(TPB, 4)
mega_k(const float* __restrict__ z,
       const float* __restrict__ t0,
       const float* __restrict__ t1,
       const float* __restrict__ t2,
       const float* __restrict__ t3,
       const float* __restrict__ t4,
       float* __restrict__ out) {
    __shared__ alignas(16) float4  sm4[3 * SLICE];   // t4 slice (3 r-slabs)
    __shared__ alignas(8)  uint64_t bar;
    __shared__ float sred[TPB / 32][3];
    __shared__ float sf[3];
    __shared__ bool  amLast;

    const int bid = blockIdx.x;
    const int tid = threadIdx.x;

    // ---- phase 0: issue TMA for this block's TT4 slice (overlaps reduce) --
    const int sl0 = bid * SLICE;                 // first s-f4 of slice
    const int cnt = min(SLICE, S4 - sl0);        // ragged last block (39)
    const uint32_t bar_b = smem_u32(&bar);
    const uint32_t sm4_b = smem_u32(sm4);

    if (tid == 0) mbar_init(bar_b, 1);
    __syncthreads();
    if (tid == 0) {
        mbar_expect_tx(bar_b, 3u * cnt * 16u);
#pragma unroll
        for (int r = 0; r < 3; r++)
            bulk_g2s(sm4_b + r * (SLICE * 16), t4 + (size_t)r * S + (size_t)sl0 * 4,
                     cnt * 16, bar_b);
    }

    // ---- phase 1: slab reduction (R3 body, ragged grid-stride) ------------
    const int slab = bid % NSLAB;                // co-schedule same s-range
    const int blk  = bid / NSLAB;                // 0..58

    const float* base;
    {
        const int r = (slab == 0) ? 0 : ((slab - 1) % 3);
        const float* t = (slab == 0) ? t0 : (slab <= 3 ? t1 : (slab <= 6 ? t2 : t3));
        base = t + (size_t)r * (3u * S);
    }
    const float4* bp = reinterpret_cast<const float4*>(base);
    const float4* zp = reinterpret_cast<const float4*>(z);

    float a0 = 0.0f, a1 = 0.0f, a2 = 0.0f;

    int c = blk * TPB + tid;                     // chunk idx, stride RSTRIDE
#pragma unroll 6
    for (int it = 0; it < NIT; it++, c += RSTRIDE) {
        if (c < S4) {
            float4 zv = zp[c];
            const float4* p = bp + (size_t)c * 3;
            float4 v0 = p[0];
            float4 v1 = p[1];
            float4 v2 = p[2];
            // 12 consecutive floats = 4 s x 3 q ; elem e -> (s=e/3, q=e%3)
            a0 += zv.x * v0.x;  a1 += zv.x * v0.y;  a2 += zv.x * v0.z;
            a0 += zv.y * v0.w;  a1 += zv.y * v1.x;  a2 += zv.y * v1.y;
            a0 += zv.z * v1.z;  a1 += zv.z * v1.w;  a2 += zv.z * v2.x;
            a0 += zv.w * v2.y;  a1 += zv.w * v2.z;  a2 += zv.w * v2.w;
        }
    }

    const unsigned FULL = 0xffffffffu;
#pragma unroll
    for (int off = 16; off >= 1; off >>= 1) {
        a0 += __shfl_down_sync(FULL, a0, off);
        a1 += __shfl_down_sync(FULL, a1, off);
        a2 += __shfl_down_sync(FULL, a2, off);
    }
    const int warp = tid >> 5;
    const int lane = tid & 31;
    if (lane == 0) { sred[warp][0] = a0; sred[warp][1] = a1; sred[warp][2] = a2; }
    __syncthreads();

    if (tid < 3) {
        float s = 0.0f;
#pragma unroll
        for (int w = 0; w < TPB / 32; w++) s += sred[w][tid];
        g_bpart[(slab * 3 + tid) * PBLK + blk] = s;   // deterministic
    }

    // ---- phase 2: last block finalizes f = V0 @ V1 @ V2 @ V3 --------------
    __threadfence();
    if (tid == 0)
        amLast = (atomicAdd(&g_ctr, 1u) == (unsigned)(RBLK - 1));
    __syncthreads();

    if (amLast) {
        __threadfence();                         // see all blocks' partials
        __shared__ float sV[NCOMP][8];
        const int comp = tid >> 3;               // 0..31 (use 0..29)
        const int part = tid & 7;
        if (comp < NCOMP) {
            float s = 0.0f;
            for (int j = part; j < PBLK; j += 8)
                s += g_bpart[comp * PBLK + j];
            sV[comp][part] = s;
        }
        __syncthreads();

        if (tid == 0) {
            float V[NCOMP];
#pragma unroll
            for (int i = 0; i < NCOMP; i++) {
                float s = 0.0f;
#pragma unroll
                for (int j = 0; j < 8; j++) s += sV[i][j];
                V[i] = s;
            }
            float f0 = V[0], f1 = V[1], f2 = V[2];        // V0 : (1,3)
#pragma unroll
            for (int cc = 0; cc < 3; cc++) {              // V1,V2,V3 (3x3 [r*3+q])
                const float* M = V + 3 + cc * 9;
                float g0 = f0 * M[0] + f1 * M[3] + f2 * M[6];
                float g1 = f0 * M[1] + f1 * M[4] + f2 * M[7];
                float g2 = f0 * M[2] + f1 * M[5] + f2 * M[8];
                f0 = g0; f1 = g1; f2 = g2;
            }
            g_f[0] = f0; g_f[1] = f1; g_f[2] = f2;
            g_ctr = 0;                            // reset for next replay
            __threadfence();                      // publish g_f before flag
            g_flag = 1;                           // release
        }
    }

    // ---- phase 3: all blocks wait for f, then bcast from smem slice -------
    if (tid == 0) {
        while (g_flag == 0) __nanosleep(64);
        __threadfence();                          // acquire g_f
        sf[0] = g_f[0]; sf[1] = g_f[1]; sf[2] = g_f[2];
    }
    __syncthreads();
    mbar_wait(bar_b, 0);                          // t4 slice resident (long done)

    const float f0 = sf[0], f1 = sf[1], f2 = sf[2];
    float4* o4 = reinterpret_cast<float4*>(out);
    for (int j = tid; j < cnt; j += TPB) {
        float4 av = sm4[j];
        float4 bv = sm4[SLICE + j];
        float4 cv = sm4[2 * SLICE + j];
        float4 o;
        o.x = f0 * av.x + f1 * bv.x + f2 * cv.x;
        o.y = f0 * av.y + f1 * bv.y + f2 * cv.y;
        o.z = f0 * av.z + f1 * bv.z + f2 * cv.z;
        o.w = f0 * av.w + f1 * bv.w + f2 * cv.w;
        o4[sl0 + j] = o;
    }

    // ---- handshake reset (last finishing block) ---------------------------
    __syncthreads();
    if (tid == 0) {
        __threadfence();
        if (atomicAdd(&g_done, 1u) == (unsigned)(RBLK - 1)) {
            g_done = 0;                           // reset for next replay
            g_flag = 0;
        }
    }
}

// ---------------------------------------------------------------------------
extern "C" void kernel_launch(void* const* d_in, const int* in_sizes, int n_in,
                              void* d_out, int out_size) {
    const float* z  = (const float*)d_in[0];
    const float* t0 = (const float*)d_in[1];
    const float* t1 = (const float*)d_in[2];
    const float* t2 = (const float*)d_in[3];
    const float* t3 = (const float*)d_in[4];
    const float* t4 = (const float*)d_in[5];
    float* out = (float*)d_out;

    mega_k<<<RBLK, TPB>>>(z, t0, t1, t2, t3, t4, out);
}

// round 11
// speedup vs baseline: 1.2053x; 1.2053x over previous
#include <cuda_runtime.h>

// Problem constants
#define S      1048576        // 1024*1024
#define S4     (S / 4)        // float4 chunks per slab (262144)
#define TPB    256
#define NSLAB  10             // TT0:r0, TT1:r0..2, TT2:r0..2, TT3:r0..2
#define PBLK   128            // reduce blocks per slab
#define NITER  (S4 / (PBLK * TPB))   // 8 grid-stride iterations per thread
#define NCOMP  30             // 10 slabs x 3 q-components
#define CBLK   592            // bcast blocks = 4 * 148 SMs (one full wave)
#define CSTR   (CBLK * TPB)   // 151552 bcast grid stride (float4 chunks)

// Deterministic scratch (no device allocation allowed)
// Layout: g_bpart[comp][PBLK]  -> contiguous per component
__device__ float g_bpart[NCOMP * PBLK];

// ---------------------------------------------------------------------------
// Kernel A: per-slab partial reduction (PROVEN R3 body — 25.6us, untouched).
//   slab = blockIdx.x % NSLAB   (same-s-range blocks co-scheduled -> z dedups)
// ---------------------------------------------------------------------------
__global__ void __launch_bounds__(TPB)
reduce_k(const float* __restrict__ z,
         const float* __restrict__ t0,
         const float* __restrict__ t1,
         const float* __restrict__ t2,
         const float* __restrict__ t3) {
    const int slab = blockIdx.x % NSLAB;
    const int blk  = blockIdx.x / NSLAB;

    const float* base;
    {
        const int r = (slab == 0) ? 0 : ((slab - 1) % 3);
        const float* t = (slab == 0) ? t0 : (slab <= 3 ? t1 : (slab <= 6 ? t2 : t3));
        base = t + (size_t)r * (3u * S);
    }
    const float4* bp = reinterpret_cast<const float4*>(base);
    const float4* zp = reinterpret_cast<const float4*>(z);

    float a0 = 0.0f, a1 = 0.0f, a2 = 0.0f;

    int c = blk * TPB + threadIdx.x;               // chunk index, stride PBLK*TPB
#pragma unroll
    for (int it = 0; it < NITER; it++, c += PBLK * TPB) {
        float4 zv = zp[c];
        const float4* p = bp + (size_t)c * 3;
        float4 v0 = p[0];
        float4 v1 = p[1];
        float4 v2 = p[2];
        // 12 consecutive floats = 4 s x 3 q ; elem e -> (s=e/3, q=e%3)
        a0 += zv.x * v0.x;  a1 += zv.x * v0.y;  a2 += zv.x * v0.z;
        a0 += zv.y * v0.w;  a1 += zv.y * v1.x;  a2 += zv.y * v1.y;
        a0 += zv.z * v1.z;  a1 += zv.z * v1.w;  a2 += zv.z * v2.x;
        a0 += zv.w * v2.y;  a1 += zv.w * v2.z;  a2 += zv.w * v2.w;
    }

    // Warp reduction of 3 components
    const unsigned FULL = 0xffffffffu;
#pragma unroll
    for (int off = 16; off >= 1; off >>= 1) {
        a0 += __shfl_down_sync(FULL, a0, off);
        a1 += __shfl_down_sync(FULL, a1, off);
        a2 += __shfl_down_sync(FULL, a2, off);
    }

    __shared__ float sred[TPB / 32][3];
    const int warp = threadIdx.x >> 5;
    const int lane = threadIdx.x & 31;
    if (lane == 0) { sred[warp][0] = a0; sred[warp][1] = a1; sred[warp][2] = a2; }
    __syncthreads();

    if (threadIdx.x < 3) {
        float s = 0.0f;
#pragma unroll
        for (int w = 0; w < TPB / 32; w++) s += sred[w][threadIdx.x];
        g_bpart[(slab * 3 + threadIdx.x) * PBLK + blk] = s;   // deterministic
    }
}

// ---------------------------------------------------------------------------
// Kernel B: bcast with INLINE per-block finalize (no extra launch, no atomics).
//   1. Issue all 6 streaming t4 loads (2 chunks x 3 slabs) -> MLP 6/thread.
//   2. While loads fly, recompute f = V0@V1@V2@V3 from g_bpart (L2-resident,
//      pure function of reduce output -> identical & deterministic per block).
//   3. FMA + streaming stores.
// ---------------------------------------------------------------------------
__global__ void __launch_bounds__(TPB)
bcast_k(const float* __restrict__ t4, float* __restrict__ out) {
    const int tid  = threadIdx.x;
    const int idx0 = blockIdx.x * TPB + tid;          // chunk 0 (coalesced)
    const int idx1 = idx0 + CSTR;                     // chunk 1 (coalesced)
    const bool has1 = (idx1 < S4);

    // ---- 1. prefetch t4 (streaming: no reuse) -----------------------------
    const float4* p = reinterpret_cast<const float4*>(t4);
    float4 a0 = __ldcs(p + idx0);
    float4 b0 = __ldcs(p + S4 + idx0);
    float4 c0 = __ldcs(p + 2 * S4 + idx0);
    float4 a1 = {0,0,0,0}, b1 = {0,0,0,0}, c1 = {0,0,0,0};
    if (has1) {
        a1 = __ldcs(p + idx1);
        b1 = __ldcs(p + S4 + idx1);
        c1 = __ldcs(p + 2 * S4 + idx1);
    }

    // ---- 2. inline finalize (overlaps the in-flight DRAM loads) -----------
    __shared__ float sV[32][8];
    __shared__ float sf[3];
    const int comp = tid >> 3;            // 0..31 (use 0..29)
    const int part = tid & 7;             // 8 parts x 4 float4 = 32 f4 = 128
    {
        float s = 0.0f;
        if (comp < NCOMP) {
            const float4* pp =
                reinterpret_cast<const float4*>(g_bpart + comp * PBLK) + part * 4;
#pragma unroll
            for (int j = 0; j < 4; j++) { float4 v = pp[j]; s += v.x + v.y + v.z + v.w; }
        }
        sV[comp][part] = s;
    }
    __syncthreads();

    if (tid == 0) {
        float V[NCOMP];
#pragma unroll
        for (int i = 0; i < NCOMP; i++) {
            float s = 0.0f;
#pragma unroll
            for (int j = 0; j < 8; j++) s += sV[i][j];
            V[i] = s;
        }
        float f0 = V[0], f1 = V[1], f2 = V[2];        // V0 : (1,3)
#pragma unroll
        for (int cc = 0; cc < 3; cc++) {              // V1,V2,V3 (3x3 [r*3+q])
            const float* M = V + 3 + cc * 9;
            float g0 = f0 * M[0] + f1 * M[3] + f2 * M[6];
            float g1 = f0 * M[1] + f1 * M[4] + f2 * M[7];
            float g2 = f0 * M[2] + f1 * M[5] + f2 * M[8];
            f0 = g0; f1 = g1; f2 = g2;
        }
        sf[0] = f0; sf[1] = f1; sf[2] = f2;
    }
    __syncthreads();
    const float f0 = sf[0], f1 = sf[1], f2 = sf[2];

    // ---- 3. FMA + streaming stores ----------------------------------------
    float4* o4 = reinterpret_cast<float4*>(out);
    float4 o;
    o.x = f0 * a0.x + f1 * b0.x + f2 * c0.x;
    o.y = f0 * a0.y + f1 * b0.y + f2 * c0.y;
    o.z = f0 * a0.z + f1 * b0.z + f2 * c0.z;
    o.w = f0 * a0.w + f1 * b0.w + f2 * c0.w;
    __stcs(o4 + idx0, o);
    if (has1) {
        o.x = f0 * a1.x + f1 * b1.x + f2 * c1.x;
        o.y = f0 * a1.y + f1 * b1.y + f2 * c1.y;
        o.z = f0 * a1.z + f1 * b1.z + f2 * c1.z;
        o.w = f0 * a1.w + f1 * b1.w + f2 * c1.w;
        __stcs(o4 + idx1, o);
    }
}

// ---------------------------------------------------------------------------
extern "C" void kernel_launch(void* const* d_in, const int* in_sizes, int n_in,
                              void* d_out, int out_size) {
    const float* z  = (const float*)d_in[0];
    const float* t0 = (const float*)d_in[1];
    const float* t1 = (const float*)d_in[2];
    const float* t2 = (const float*)d_in[3];
    const float* t3 = (const float*)d_in[4];
    const float* t4 = (const float*)d_in[5];
    float* out = (float*)d_out;

    reduce_k<<<NSLAB * PBLK, TPB>>>(z, t0, t1, t2, t3);
    bcast_k<<<CBLK, TPB>>>(t4, out);
}

// round 12
// speedup vs baseline: 1.2695x; 1.0533x over previous
#include <cuda_runtime.h>

// Problem constants
#define S      1048576        // 1024*1024
#define S4     (S / 4)        // float4 chunks per slab (262144)
#define TPB    256
#define NSLAB  10             // TT0:r0, TT1:r0..2, TT2:r0..2, TT3:r0..2
#define PBLK   128            // reduce blocks per slab
#define NITER  (S4 / (PBLK * TPB))   // 8 grid-stride iterations per thread
#define NCOMP  30             // 10 slabs x 3 q-components
#define CBLK   1024           // bcast blocks: 1024*256 = S4 exactly (R3 shape)

// Deterministic scratch (no device allocation allowed)
// Layout: g_bpart[comp][PBLK]  -> contiguous per component
__device__ float g_bpart[NCOMP * PBLK];

// ---------------------------------------------------------------------------
// Kernel A: per-slab partial reduction (R3 body + streaming loads for slabs).
//   slab = blockIdx.x % NSLAB   (same-s-range blocks co-scheduled -> z dedups)
// ---------------------------------------------------------------------------
__global__ void __launch_bounds__(TPB)
reduce_k(const float* __restrict__ z,
         const float* __restrict__ t0,
         const float* __restrict__ t1,
         const float* __restrict__ t2,
         const float* __restrict__ t3) {
    const int slab = blockIdx.x % NSLAB;
    const int blk  = blockIdx.x / NSLAB;

    const float* base;
    {
        const int r = (slab == 0) ? 0 : ((slab - 1) % 3);
        const float* t = (slab == 0) ? t0 : (slab <= 3 ? t1 : (slab <= 6 ? t2 : t3));
        base = t + (size_t)r * (3u * S);
    }
    const float4* bp = reinterpret_cast<const float4*>(base);
    const float4* zp = reinterpret_cast<const float4*>(z);

    float a0 = 0.0f, a1 = 0.0f, a2 = 0.0f;

    int c = blk * TPB + threadIdx.x;               // chunk index, stride PBLK*TPB
#pragma unroll
    for (int it = 0; it < NITER; it++, c += PBLK * TPB) {
        float4 zv = zp[c];                          // reused across 10 slabs -> cache
        const float4* p = bp + (size_t)c * 3;
        float4 v0 = __ldcs(p + 0);                  // streaming: zero reuse
        float4 v1 = __ldcs(p + 1);
        float4 v2 = __ldcs(p + 2);
        // 12 consecutive floats = 4 s x 3 q ; elem e -> (s=e/3, q=e%3)
        a0 += zv.x * v0.x;  a1 += zv.x * v0.y;  a2 += zv.x * v0.z;
        a0 += zv.y * v0.w;  a1 += zv.y * v1.x;  a2 += zv.y * v1.y;
        a0 += zv.z * v1.z;  a1 += zv.z * v1.w;  a2 += zv.z * v2.x;
        a0 += zv.w * v2.y;  a1 += zv.w * v2.z;  a2 += zv.w * v2.w;
    }

    // Warp reduction of 3 components
    const unsigned FULL = 0xffffffffu;
#pragma unroll
    for (int off = 16; off >= 1; off >>= 1) {
        a0 += __shfl_down_sync(FULL, a0, off);
        a1 += __shfl_down_sync(FULL, a1, off);
        a2 += __shfl_down_sync(FULL, a2, off);
    }

    __shared__ float sred[TPB / 32][3];
    const int warp = threadIdx.x >> 5;
    const int lane = threadIdx.x & 31;
    if (lane == 0) { sred[warp][0] = a0; sred[warp][1] = a1; sred[warp][2] = a2; }
    __syncthreads();

    if (threadIdx.x < 3) {
        float s = 0.0f;
#pragma unroll
        for (int w = 0; w < TPB / 32; w++) s += sred[w][threadIdx.x];
        g_bpart[(slab * 3 + threadIdx.x) * PBLK + blk] = s;   // deterministic
    }
}

// ---------------------------------------------------------------------------
// Kernel B: bcast with inline finalize (R3's fast 1024-block / 3-load shape).
//   1. Issue the 3 streaming t4 loads.
//   2. While they fly, recompute f = V0@V1@V2@V3 from g_bpart (L2-resident,
//      pure function of reduce output -> deterministic, identical per block).
//   3. FMA + streaming store.
// ---------------------------------------------------------------------------
__global__ void __launch_bounds__(TPB)
bcast_k(const float* __restrict__ t4, float* __restrict__ out) {
    const int tid = threadIdx.x;
    const int idx = blockIdx.x * TPB + tid;           // 0 .. S4-1 (exact)

    // ---- 1. prefetch t4 (streaming: no reuse) -----------------------------
    const float4* p = reinterpret_cast<const float4*>(t4);
    float4 av = __ldcs(p + idx);
    float4 bv = __ldcs(p + S4 + idx);
    float4 cv = __ldcs(p + 2 * S4 + idx);

    // ---- 2. inline finalize (overlaps in-flight DRAM loads) ---------------
    __shared__ float sV[32][8];
    __shared__ float sf[3];
    const int comp = tid >> 3;            // 0..31 (use 0..29)
    const int part = tid & 7;             // 8 parts x 4 float4 = 128 partials
    {
        float s = 0.0f;
        if (comp < NCOMP) {
            const float4* pp =
                reinterpret_cast<const float4*>(g_bpart + comp * PBLK) + part * 4;
#pragma unroll
            for (int j = 0; j < 4; j++) { float4 v = pp[j]; s += v.x + v.y + v.z + v.w; }
        }
        sV[comp][part] = s;
    }
    __syncthreads();

    if (tid == 0) {
        float V[NCOMP];
#pragma unroll
        for (int i = 0; i < NCOMP; i++) {
            float s = 0.0f;
#pragma unroll
            for (int j = 0; j < 8; j++) s += sV[i][j];
            V[i] = s;
        }
        float f0 = V[0], f1 = V[1], f2 = V[2];        // V0 : (1,3)
#pragma unroll
        for (int cc = 0; cc < 3; cc++) {              // V1,V2,V3 (3x3 [r*3+q])
            const float* M = V + 3 + cc * 9;
            float g0 = f0 * M[0] + f1 * M[3] + f2 * M[6];
            float g1 = f0 * M[1] + f1 * M[4] + f2 * M[7];
            float g2 = f0 * M[2] + f1 * M[5] + f2 * M[8];
            f0 = g0; f1 = g1; f2 = g2;
        }
        sf[0] = f0; sf[1] = f1; sf[2] = f2;
    }
    __syncthreads();
    const float f0 = sf[0], f1 = sf[1], f2 = sf[2];

    // ---- 3. FMA + streaming store -----------------------------------------
    float4 o;
    o.x = f0 * av.x + f1 * bv.x + f2 * cv.x;
    o.y = f0 * av.y + f1 * bv.y + f2 * cv.y;
    o.z = f0 * av.z + f1 * bv.z + f2 * cv.z;
    o.w = f0 * av.w + f1 * bv.w + f2 * cv.w;
    __stcs(reinterpret_cast<float4*>(out) + idx, o);
}

// ---------------------------------------------------------------------------
extern "C" void kernel_launch(void* const* d_in, const int* in_sizes, int n_in,
                              void* d_out, int out_size) {
    const float* z  = (const float*)d_in[0];
    const float* t0 = (const float*)d_in[1];
    const float* t1 = (const float*)d_in[2];
    const float* t2 = (const float*)d_in[3];
    const float* t3 = (const float*)d_in[4];
    const float* t4 = (const float*)d_in[5];
    float* out = (float*)d_out;

    reduce_k<<<NSLAB * PBLK, TPB>>>(z, t0, t1, t2, t3);
    bcast_k<<<CBLK, TPB>>>(t4, out);
}